// round 5
// baseline (speedup 1.0000x reference)
#include <cuda_runtime.h>
#include <cuda_fp16.h>
#include <cstdint>
#include <cstddef>

// ---------------------------------------------------------------------------
// GraphSAGE 2-layer, sm_103a.
//   h   = relu( scatter_mean(x, src->dst) @ Wl1^T + bl1 + x @ Wr1^T )
//   out =       scatter_mean(h, src->dst) @ Wl2^T + bl2 + h @ Wr2^T
// Round 4: fp16 feature mirrors for the gather (halves L2 gather traffic);
//          gather = half-warp per node; binning reads edge_index directly.
// GEMMs remain full-fp32 FFMA2 (fma.rn.f32x2).
// ---------------------------------------------------------------------------

#define MAX_N 100000
#define MAX_E 1600000
#define D_IN  128
#define D_HID 128
#define D_OUT 64

typedef unsigned long long ull;

// Scratch (device globals: no allocation allowed in kernel_launch)
__device__ float  g_agg[(size_t)MAX_N * 128];
__device__ float  g_h[(size_t)MAX_N * 128];
__device__ __half g_x16[(size_t)MAX_N * 128];
__device__ __half g_h16[(size_t)MAX_N * 128];
__device__ int    g_bin[MAX_E];          // src ids grouped by dst
__device__ int    g_cnt[MAX_N + 1];
__device__ int    g_off[MAX_N + 1];
__device__ int    g_cur[MAX_N + 1];
__device__ int    g_bsum[128];
__device__ int    g_is64;

// ---------------------------------------------------------------------------
// Edge-index dtype detection (int64 vs int32 payload).
// ---------------------------------------------------------------------------
__global__ void detect_idx_kernel(const long long* __restrict__ ei, int E, long long N) {
    __shared__ int bad;
    if (threadIdx.x == 0) bad = 0;
    __syncthreads();
    int i = threadIdx.x;
    if (i < E) {
        long long v = ei[i];
        if (v < 0 || v >= N) atomicAdd(&bad, 1);
    }
    __syncthreads();
    if (threadIdx.x == 0) g_is64 = (bad == 0) ? 1 : 0;
}

// ---------------------------------------------------------------------------
// CSR binning straight from edge_index: count -> scan -> fill
// ---------------------------------------------------------------------------
__global__ void count_kernel(const void* __restrict__ ei, int* __restrict__ cnt, int E) {
    int i = blockIdx.x * blockDim.x + threadIdx.x;
    if (i >= E) return;
    int d = g_is64 ? (int)((const long long*)ei)[(size_t)E + i]
                   : ((const int*)ei)[(size_t)E + i];
    atomicAdd(&cnt[d], 1);
}

__global__ void scan_block_kernel(const int* __restrict__ cnt, int* __restrict__ off,
                                  int* __restrict__ bsum, int N) {
    __shared__ int sm[1024];
    int tid = threadIdx.x;
    int gi  = blockIdx.x * 1024 + tid;
    int v   = (gi < N) ? cnt[gi] : 0;
    sm[tid] = v;
    __syncthreads();
#pragma unroll
    for (int s = 1; s < 1024; s <<= 1) {
        int t = (tid >= s) ? sm[tid - s] : 0;
        __syncthreads();
        sm[tid] += t;
        __syncthreads();
    }
    if (gi < N) off[gi] = sm[tid] - v;     // exclusive
    if (tid == 1023) bsum[blockIdx.x] = sm[1023];
}

__global__ void scan_bsum_kernel(int* __restrict__ bsum, int nb) {
    if (threadIdx.x == 0) {
        int run = 0;
        for (int i = 0; i < nb; i++) { int t = bsum[i]; bsum[i] = run; run += t; }
    }
}

__global__ void add_off_kernel(int* __restrict__ off, const int* __restrict__ bsum,
                               int N, int E) {
    int gi = blockIdx.x * blockDim.x + threadIdx.x;
    if (gi < N) off[gi] += bsum[gi >> 10];
    if (gi == 0) off[N] = E;
}

__global__ void fill_kernel(const void* __restrict__ ei, int E,
                            int* __restrict__ cur, int* __restrict__ bin) {
    int i = blockIdx.x * blockDim.x + threadIdx.x;
    if (i >= E) return;
    int s, d;
    if (g_is64) {
        const long long* p = (const long long*)ei;
        s = (int)p[i];
        d = (int)p[(size_t)E + i];
    } else {
        const int* p = (const int*)ei;
        s = p[i];
        d = p[(size_t)E + i];
    }
    int pos = atomicAdd(&cur[d], 1);
    bin[pos] = s;
}

// ---------------------------------------------------------------------------
// fp32 -> fp16 mirror
// ---------------------------------------------------------------------------
__global__ void tohalf_kernel(const float2* __restrict__ in, __half2* __restrict__ out, int n2) {
    int i = blockIdx.x * blockDim.x + threadIdx.x;
    if (i < n2) out[i] = __float22half2_rn(in[i]);
}

// ---------------------------------------------------------------------------
// Gather-mean over fp16 features, fp32 accumulate. Half-warp (16 lanes) per
// node; each lane owns 8 halves (16B) of the 256B row. Writes fp32 agg.
// ---------------------------------------------------------------------------
__device__ __forceinline__ void acc_u4(float* acc, uint4 v) {
    float2 f;
    f = __half22float2(*(const __half2*)&v.x); acc[0] += f.x; acc[1] += f.y;
    f = __half22float2(*(const __half2*)&v.y); acc[2] += f.x; acc[3] += f.y;
    f = __half22float2(*(const __half2*)&v.z); acc[4] += f.x; acc[5] += f.y;
    f = __half22float2(*(const __half2*)&v.w); acc[6] += f.x; acc[7] += f.y;
}

__global__ void gather_kernel(const uint4* __restrict__ feat,   // fp16 rows, 16 uint4/row
                              const int* __restrict__ off,
                              const int* __restrict__ bin,
                              float4* __restrict__ agg, int N) {
    int warp = (blockIdx.x * blockDim.x + threadIdx.x) >> 5;
    int lane = threadIdx.x & 31;
    int node = warp * 2 + (lane >> 4);
    int l16  = lane & 15;
    if (node >= N) return;
    int s0 = off[node], s1 = off[node + 1];
    float acc[8];
#pragma unroll
    for (int i = 0; i < 8; i++) acc[i] = 0.0f;
    int e = s0;
    for (; e + 4 <= s1; e += 4) {
        int i0 = bin[e], i1 = bin[e + 1], i2 = bin[e + 2], i3 = bin[e + 3];
        uint4 v0 = feat[(size_t)i0 * 16 + l16];
        uint4 v1 = feat[(size_t)i1 * 16 + l16];
        uint4 v2 = feat[(size_t)i2 * 16 + l16];
        uint4 v3 = feat[(size_t)i3 * 16 + l16];
        acc_u4(acc, v0); acc_u4(acc, v1); acc_u4(acc, v2); acc_u4(acc, v3);
    }
    for (; e < s1; e++) {
        uint4 v = feat[(size_t)bin[e] * 16 + l16];
        acc_u4(acc, v);
    }
    float sc = 1.0f / (float)max(s1 - s0, 1);
#pragma unroll
    for (int i = 0; i < 8; i++) acc[i] *= sc;
    float4* p = agg + (size_t)node * 32 + l16 * 2;
    p[0] = make_float4(acc[0], acc[1], acc[2], acc[3]);
    p[1] = make_float4(acc[4], acc[5], acc[6], acc[7]);
}

// ---------------------------------------------------------------------------
// Fused dual GEMM on packed fp32 (fma.rn.f32x2), K paired.
//   A = [agg | x] (K=256), W = [Wl ; Wr] stacked, both staged k-paired.
// TM=128 nodes/CTA. Thread tile 4x8. Optional fp16 secondary output (h16).
// ---------------------------------------------------------------------------
__device__ __forceinline__ void ffma2(ull& d, ull a, ull b) {
    asm("fma.rn.f32x2 %0, %1, %2, %3;" : "=l"(d) : "l"(a), "l"(b), "l"(d));
}

template <int TN>
__global__ void __launch_bounds__(32 * (TN / 8), 1)
sage_gemm_kernel(const float* __restrict__ agg,
                 const float* __restrict__ xin,
                 const float* __restrict__ Wl, const float* __restrict__ Wr,
                 const float* __restrict__ bias,
                 float* __restrict__ out, __half* __restrict__ out16,
                 int N, int do_relu) {
    constexpr int TM     = 128;
    constexpr int NT     = 32 * (TN / 8);
    constexpr int K2     = 128;          // 256 k / 2
    constexpr int KC2    = 32;           // k-pairs per chunk (KC=64)
    constexpr int WROW2  = TN + 2;
    constexpr int AROW2  = TM + 2;

    extern __shared__ float2 smem2[];
    float2* Wc = smem2;                          // [K2][WROW2]
    float2* At = smem2 + K2 * WROW2;             // [2][KC2][AROW2]

    const int tid   = threadIdx.x;
    const int lane  = tid & 31;                  // rows lane*4..+3
    const int wid   = tid >> 5;                  // cols wid*8..+7
    const int node0 = blockIdx.x * TM;

    for (int idx = tid; idx < 64 * TN; idx += NT) {
        int j  = idx >> 6;
        int k2 = idx & 63;
        Wc[k2 * WROW2 + j]        = *(const float2*)(Wl + j * 128 + 2 * k2);
        Wc[(64 + k2) * WROW2 + j] = *(const float2*)(Wr + j * 128 + 2 * k2);
    }

    ull acc[4][8];
#pragma unroll
    for (int i = 0; i < 4; i++)
#pragma unroll
        for (int j = 0; j < 8; j++) acc[i][j] = 0ULL;

    auto loadA = [&](int buf, int kc) {
        float2* db = At + buf * (KC2 * AROW2);
#pragma unroll 4
        for (int idx = tid; idx < KC2 * TM; idx += NT) {
            int k2   = idx & (KC2 - 1);
            int node = idx >> 5;
            int k    = kc * 64 + 2 * k2;
            int n    = node0 + node;
            float2 v = make_float2(0.f, 0.f);
            if (n < N) {
                v = (k < 128) ? *(const float2*)(agg + (size_t)n * 128 + k)
                              : *(const float2*)(xin + (size_t)n * 128 + (k - 128));
            }
            db[k2 * AROW2 + node] = v;
        }
    };

    loadA(0, 0);
    __syncthreads();   // covers Wc too

#pragma unroll 1
    for (int kc = 0; kc < 4; kc++) {
        int b = kc & 1;
        if (kc < 3) loadA(b ^ 1, kc + 1);
        const float2* Ab = At + b * (KC2 * AROW2);
        const float2* Wb = Wc + (kc * KC2) * WROW2;
#pragma unroll 4
        for (int kk2 = 0; kk2 < KC2; kk2++) {
            const float2* ar = Ab + kk2 * AROW2 + lane * 4;
            const float2* wr = Wb + kk2 * WROW2 + wid * 8;
            ull a[4], w[8];
            {
                ulonglong2 t;
                t = *(const ulonglong2*)(ar);     a[0] = t.x; a[1] = t.y;
                t = *(const ulonglong2*)(ar + 2); a[2] = t.x; a[3] = t.y;
                t = *(const ulonglong2*)(wr);     w[0] = t.x; w[1] = t.y;
                t = *(const ulonglong2*)(wr + 2); w[2] = t.x; w[3] = t.y;
                t = *(const ulonglong2*)(wr + 4); w[4] = t.x; w[5] = t.y;
                t = *(const ulonglong2*)(wr + 6); w[6] = t.x; w[7] = t.y;
            }
#pragma unroll
            for (int i = 0; i < 4; i++)
#pragma unroll
                for (int j = 0; j < 8; j++) ffma2(acc[i][j], a[i], w[j]);
        }
        __syncthreads();
    }

    float bv[8];
#pragma unroll
    for (int j = 0; j < 8; j++) bv[j] = bias[wid * 8 + j];

#pragma unroll
    for (int i = 0; i < 4; i++) {
        int n = node0 + lane * 4 + i;
        if (n < N) {
            float r[8];
#pragma unroll
            for (int j = 0; j < 8; j++) {
                float2 p = *(float2*)&acc[i][j];
                float v  = p.x + p.y + bv[j];
                r[j] = do_relu ? fmaxf(v, 0.0f) : v;
            }
            *(float4*)(out + (size_t)n * TN + wid * 8)     = make_float4(r[0], r[1], r[2], r[3]);
            *(float4*)(out + (size_t)n * TN + wid * 8 + 4) = make_float4(r[4], r[5], r[6], r[7]);
            if (out16) {
                __half2 hh[4];
                hh[0] = __floats2half2_rn(r[0], r[1]);
                hh[1] = __floats2half2_rn(r[2], r[3]);
                hh[2] = __floats2half2_rn(r[4], r[5]);
                hh[3] = __floats2half2_rn(r[6], r[7]);
                *(uint4*)(out16 + (size_t)n * TN + wid * 8) = *(uint4*)hh;
            }
        }
    }
}

// ---------------------------------------------------------------------------

extern "C" void kernel_launch(void* const* d_in, const int* in_sizes, int n_in,
                              void* d_out, int out_size) {
    const float* x   = (const float*)d_in[0];
    const void*  ei  = d_in[1];
    const float* Wl1 = (const float*)d_in[2];
    const float* bl1 = (const float*)d_in[3];
    const float* Wr1 = (const float*)d_in[4];
    const float* Wl2 = (const float*)d_in[5];
    const float* bl2 = (const float*)d_in[6];
    const float* Wr2 = (const float*)d_in[7];
    float* out = (float*)d_out;

    int N = in_sizes[0] / D_IN;
    int E = in_sizes[1] / 2;

    float *agg, *h;
    __half *x16, *h16;
    int *bin, *cnt, *off, *cur, *bsum;
    cudaGetSymbolAddress((void**)&agg,  g_agg);
    cudaGetSymbolAddress((void**)&h,    g_h);
    cudaGetSymbolAddress((void**)&x16,  g_x16);
    cudaGetSymbolAddress((void**)&h16,  g_h16);
    cudaGetSymbolAddress((void**)&bin,  g_bin);
    cudaGetSymbolAddress((void**)&cnt,  g_cnt);
    cudaGetSymbolAddress((void**)&off,  g_off);
    cudaGetSymbolAddress((void**)&cur,  g_cur);
    cudaGetSymbolAddress((void**)&bsum, g_bsum);

    constexpr int SMEM1 = (128 * (128 + 2) + 2 * 32 * (128 + 2)) * 8;  // 199680 B
    constexpr int SMEM2 = (128 * (64 + 2)  + 2 * 32 * (128 + 2)) * 8;  // 134144 B
    cudaFuncSetAttribute(sage_gemm_kernel<128>, cudaFuncAttributeMaxDynamicSharedMemorySize, SMEM1);
    cudaFuncSetAttribute(sage_gemm_kernel<64>,  cudaFuncAttributeMaxDynamicSharedMemorySize, SMEM2);

    const int TB = 256;
    int nbE = (E + TB - 1) / TB;
    int nbScan = (N + 1023) / 1024;

    // --- edge normalization + CSR binning (shared by both layers) ---
    detect_idx_kernel<<<1, 256>>>((const long long*)ei, E, (long long)N);
    cudaMemsetAsync(cnt, 0, (size_t)(N + 1) * sizeof(int));
    count_kernel<<<nbE, TB>>>(ei, cnt, E);
    scan_block_kernel<<<nbScan, 1024>>>(cnt, off, bsum, N);
    scan_bsum_kernel<<<1, 32>>>(bsum, nbScan);
    add_off_kernel<<<(N + TB - 1) / TB, TB>>>(off, bsum, N, E);
    cudaMemcpyAsync(cur, off, (size_t)(N + 1) * sizeof(int), cudaMemcpyDeviceToDevice);
    fill_kernel<<<nbE, TB>>>(ei, E, cur, bin);

    // fp16 mirror of x (overlaps with binning work in issue order)
    int n2 = N * 64;
    tohalf_kernel<<<(n2 + TB - 1) / TB, TB>>>((const float2*)x, (__half2*)x16, n2);

    int nbGather = ((N + 1) / 2 * 32 + TB - 1) / TB;

    // --- layer 1 ---
    gather_kernel<<<nbGather, TB>>>((const uint4*)x16, off, bin, (float4*)agg, N);
    sage_gemm_kernel<128><<<(N + 127) / 128, 512, SMEM1>>>(agg, x, Wl1, Wr1, bl1, h, h16, N, 1);

    // --- layer 2 ---
    gather_kernel<<<nbGather, TB>>>((const uint4*)h16, off, bin, (float4*)agg, N);
    sage_gemm_kernel<64><<<(N + 127) / 128, 256, SMEM2>>>(agg, h, Wl2, Wr2, bl2, out, (__half*)nullptr, N, 0);
}

// round 6
// speedup vs baseline: 1.2713x; 1.2713x over previous
#include <cuda_runtime.h>
#include <cstdint>
#include <cstddef>

// ---------------------------------------------------------------------------
// GraphSAGE 2-layer, sm_103a.
//   h   = relu( scatter_mean(x, src->dst) @ Wl1^T + bl1 + x @ Wr1^T )
//   out =       scatter_mean(h, src->dst) @ Wl2^T + bl2 + h @ Wr2^T
// Round 5: fp32 gathers with packed add.rn.f32x2; layer-2 restructured as
//   z = h@Wl2^T, r = h@Wr2^T  (one GEMM),  out = mean_gather(z) + bl2 + r
// exploiting linearity of the mean (gather-2 rows are 64-wide, half cost).
// GEMMs: full-fp32 FFMA2 (fma.rn.f32x2).
// ---------------------------------------------------------------------------

#define MAX_N 100000
#define MAX_E 1600000
#define D_IN  128

typedef unsigned long long ull;

// Scratch (device globals: no allocation allowed in kernel_launch)
__device__ float g_agg[(size_t)MAX_N * 128];   // layer1 agg; layer2 reuses as z|r
__device__ float g_h[(size_t)MAX_N * 128];
__device__ int   g_bin[MAX_E];
__device__ int   g_cnt[MAX_N + 1];
__device__ int   g_off[MAX_N + 1];
__device__ int   g_cur[MAX_N + 1];
__device__ int   g_bsum[128];
__device__ int   g_is64;

__device__ __forceinline__ void ffma2(ull& d, ull a, ull b) {
    asm("fma.rn.f32x2 %0, %1, %2, %3;" : "=l"(d) : "l"(a), "l"(b), "l"(d));
}
__device__ __forceinline__ void fadd2(ull& d, ull a) {
    asm("add.rn.f32x2 %0, %1, %2;" : "=l"(d) : "l"(a), "l"(d));
}

// ---------------------------------------------------------------------------
// Edge-index dtype detection (int64 vs int32 payload).
// ---------------------------------------------------------------------------
__global__ void detect_idx_kernel(const long long* __restrict__ ei, int E, long long N) {
    __shared__ int bad;
    if (threadIdx.x == 0) bad = 0;
    __syncthreads();
    int i = threadIdx.x;
    if (i < E) {
        long long v = ei[i];
        if (v < 0 || v >= N) atomicAdd(&bad, 1);
    }
    __syncthreads();
    if (threadIdx.x == 0) g_is64 = (bad == 0) ? 1 : 0;
}

// ---------------------------------------------------------------------------
// CSR binning straight from edge_index: count -> scan -> fill
// ---------------------------------------------------------------------------
__global__ void count_kernel(const void* __restrict__ ei, int* __restrict__ cnt, int E) {
    int i = blockIdx.x * blockDim.x + threadIdx.x;
    if (i >= E) return;
    int d = g_is64 ? (int)((const long long*)ei)[(size_t)E + i]
                   : ((const int*)ei)[(size_t)E + i];
    atomicAdd(&cnt[d], 1);
}

__global__ void scan_block_kernel(const int* __restrict__ cnt, int* __restrict__ off,
                                  int* __restrict__ bsum, int N) {
    __shared__ int sm[1024];
    int tid = threadIdx.x;
    int gi  = blockIdx.x * 1024 + tid;
    int v   = (gi < N) ? cnt[gi] : 0;
    sm[tid] = v;
    __syncthreads();
#pragma unroll
    for (int s = 1; s < 1024; s <<= 1) {
        int t = (tid >= s) ? sm[tid - s] : 0;
        __syncthreads();
        sm[tid] += t;
        __syncthreads();
    }
    if (gi < N) off[gi] = sm[tid] - v;     // exclusive
    if (tid == 1023) bsum[blockIdx.x] = sm[1023];
}

__global__ void scan_bsum_kernel(int* __restrict__ bsum, int nb) {
    if (threadIdx.x == 0) {
        int run = 0;
        for (int i = 0; i < nb; i++) { int t = bsum[i]; bsum[i] = run; run += t; }
    }
}

__global__ void add_off_kernel(int* __restrict__ off, const int* __restrict__ bsum,
                               int N, int E) {
    int gi = blockIdx.x * blockDim.x + threadIdx.x;
    if (gi < N) off[gi] += bsum[gi >> 10];
    if (gi == 0) off[N] = E;
}

__global__ void fill_kernel(const void* __restrict__ ei, int E,
                            int* __restrict__ cur, int* __restrict__ bin) {
    int i = blockIdx.x * blockDim.x + threadIdx.x;
    if (i >= E) return;
    int s, d;
    if (g_is64) {
        const long long* p = (const long long*)ei;
        s = (int)p[i];
        d = (int)p[(size_t)E + i];
    } else {
        const int* p = (const int*)ei;
        s = p[i];
        d = p[(size_t)E + i];
    }
    int pos = atomicAdd(&cur[d], 1);
    bin[pos] = s;
}

// ---------------------------------------------------------------------------
// Gather-mean, 128-wide fp32 rows. One warp per node; lane owns 16B chunk.
// Packed f32x2 accumulation: 1 LDG.128 + 2 adds per chunk.
// ---------------------------------------------------------------------------
__global__ void gather128_kernel(const ulonglong2* __restrict__ feat,  // 32 u2/row
                                 const int* __restrict__ off,
                                 const int* __restrict__ bin,
                                 float4* __restrict__ agg, int N) {
    int node = (blockIdx.x * blockDim.x + threadIdx.x) >> 5;
    int lane = threadIdx.x & 31;
    if (node >= N) return;
    int s0 = off[node], s1 = off[node + 1];
    ull a0 = 0, a1 = 0;
    int e = s0;
    for (; e + 4 <= s1; e += 4) {
        int i0 = bin[e], i1 = bin[e + 1], i2 = bin[e + 2], i3 = bin[e + 3];
        ulonglong2 v0 = feat[(size_t)i0 * 32 + lane];
        ulonglong2 v1 = feat[(size_t)i1 * 32 + lane];
        ulonglong2 v2 = feat[(size_t)i2 * 32 + lane];
        ulonglong2 v3 = feat[(size_t)i3 * 32 + lane];
        fadd2(a0, v0.x); fadd2(a1, v0.y);
        fadd2(a0, v1.x); fadd2(a1, v1.y);
        fadd2(a0, v2.x); fadd2(a1, v2.y);
        fadd2(a0, v3.x); fadd2(a1, v3.y);
    }
    for (; e < s1; e++) {
        ulonglong2 v = feat[(size_t)bin[e] * 32 + lane];
        fadd2(a0, v.x); fadd2(a1, v.y);
    }
    float sc = 1.0f / (float)max(s1 - s0, 1);
    float2 p0 = *(float2*)&a0, p1 = *(float2*)&a1;
    agg[(size_t)node * 32 + lane] =
        make_float4(p0.x * sc, p0.y * sc, p1.x * sc, p1.y * sc);
}

// ---------------------------------------------------------------------------
// Gather-mean over 64-wide z rows + fused epilogue: out = mean + bias + r.
// Half-warp (16 lanes) per node.
// ---------------------------------------------------------------------------
__global__ void gather64_add_kernel(const ulonglong2* __restrict__ z,   // 16 u2/row
                                    const int* __restrict__ off,
                                    const int* __restrict__ bin,
                                    const float4* __restrict__ r,       // 16 f4/row
                                    const float* __restrict__ bias,
                                    float4* __restrict__ out, int N) {
    int warp = (blockIdx.x * blockDim.x + threadIdx.x) >> 5;
    int lane = threadIdx.x & 31;
    int node = warp * 2 + (lane >> 4);
    int l16  = lane & 15;
    if (node >= N) return;
    int s0 = off[node], s1 = off[node + 1];
    ull a0 = 0, a1 = 0;
    int e = s0;
    for (; e + 4 <= s1; e += 4) {
        int i0 = bin[e], i1 = bin[e + 1], i2 = bin[e + 2], i3 = bin[e + 3];
        ulonglong2 v0 = z[(size_t)i0 * 16 + l16];
        ulonglong2 v1 = z[(size_t)i1 * 16 + l16];
        ulonglong2 v2 = z[(size_t)i2 * 16 + l16];
        ulonglong2 v3 = z[(size_t)i3 * 16 + l16];
        fadd2(a0, v0.x); fadd2(a1, v0.y);
        fadd2(a0, v1.x); fadd2(a1, v1.y);
        fadd2(a0, v2.x); fadd2(a1, v2.y);
        fadd2(a0, v3.x); fadd2(a1, v3.y);
    }
    for (; e < s1; e++) {
        ulonglong2 v = z[(size_t)bin[e] * 16 + l16];
        fadd2(a0, v.x); fadd2(a1, v.y);
    }
    float sc = 1.0f / (float)max(s1 - s0, 1);
    float2 p0 = *(float2*)&a0, p1 = *(float2*)&a1;
    float4 rv = r[(size_t)node * 16 + l16];
    float4 bv = __ldg((const float4*)bias + l16);
    out[(size_t)node * 16 + l16] =
        make_float4(p0.x * sc + bv.x + rv.x, p0.y * sc + bv.y + rv.y,
                    p1.x * sc + bv.z + rv.z, p1.y * sc + bv.w + rv.w);
}

// ---------------------------------------------------------------------------
// Layer-1 fused dual GEMM on packed fp32 FFMA2, K paired (K=256):
//   h = relu([agg | x] @ [Wl1 ; Wr1]^T + bl1)
// TM=128 nodes/CTA, 512 threads, thread tile 4x8.
// ---------------------------------------------------------------------------
__global__ void __launch_bounds__(512, 1)
sage_gemm1_kernel(const float* __restrict__ agg,
                  const float* __restrict__ xin,
                  const float* __restrict__ Wl, const float* __restrict__ Wr,
                  const float* __restrict__ bias,
                  float* __restrict__ out, int N) {
    constexpr int TM    = 128;
    constexpr int TN    = 128;
    constexpr int NT    = 512;
    constexpr int KC2   = 32;            // k-pairs per chunk (KC=64)
    constexpr int WROW2 = TN + 2;
    constexpr int AROW2 = TM + 2;

    extern __shared__ float2 smem2[];
    float2* Wc = smem2;                          // [128][WROW2]
    float2* At = smem2 + 128 * WROW2;            // [2][KC2][AROW2]

    const int tid   = threadIdx.x;
    const int lane  = tid & 31;
    const int wid   = tid >> 5;
    const int node0 = blockIdx.x * TM;

    for (int idx = tid; idx < 64 * TN; idx += NT) {
        int j  = idx >> 6;
        int k2 = idx & 63;
        Wc[k2 * WROW2 + j]        = *(const float2*)(Wl + j * 128 + 2 * k2);
        Wc[(64 + k2) * WROW2 + j] = *(const float2*)(Wr + j * 128 + 2 * k2);
    }

    ull acc[4][8];
#pragma unroll
    for (int i = 0; i < 4; i++)
#pragma unroll
        for (int j = 0; j < 8; j++) acc[i][j] = 0ULL;

    auto loadA = [&](int buf, int kc) {
        float2* db = At + buf * (KC2 * AROW2);
#pragma unroll 4
        for (int idx = tid; idx < KC2 * TM; idx += NT) {
            int k2   = idx & (KC2 - 1);
            int node = idx >> 5;
            int k    = kc * 64 + 2 * k2;
            int n    = node0 + node;
            float2 v = make_float2(0.f, 0.f);
            if (n < N) {
                v = (k < 128) ? *(const float2*)(agg + (size_t)n * 128 + k)
                              : *(const float2*)(xin + (size_t)n * 128 + (k - 128));
            }
            db[k2 * AROW2 + node] = v;
        }
    };

    loadA(0, 0);
    __syncthreads();

#pragma unroll 1
    for (int kc = 0; kc < 4; kc++) {
        int b = kc & 1;
        if (kc < 3) loadA(b ^ 1, kc + 1);
        const float2* Ab = At + b * (KC2 * AROW2);
        const float2* Wb = Wc + (kc * KC2) * WROW2;
#pragma unroll 4
        for (int kk2 = 0; kk2 < KC2; kk2++) {
            const float2* ar = Ab + kk2 * AROW2 + lane * 4;
            const float2* wr = Wb + kk2 * WROW2 + wid * 8;
            ull a[4], w[8];
            ulonglong2 t;
            t = *(const ulonglong2*)(ar);     a[0] = t.x; a[1] = t.y;
            t = *(const ulonglong2*)(ar + 2); a[2] = t.x; a[3] = t.y;
            t = *(const ulonglong2*)(wr);     w[0] = t.x; w[1] = t.y;
            t = *(const ulonglong2*)(wr + 2); w[2] = t.x; w[3] = t.y;
            t = *(const ulonglong2*)(wr + 4); w[4] = t.x; w[5] = t.y;
            t = *(const ulonglong2*)(wr + 6); w[6] = t.x; w[7] = t.y;
#pragma unroll
            for (int i = 0; i < 4; i++)
#pragma unroll
                for (int j = 0; j < 8; j++) ffma2(acc[i][j], a[i], w[j]);
        }
        __syncthreads();
    }

    float bv[8];
#pragma unroll
    for (int j = 0; j < 8; j++) bv[j] = bias[wid * 8 + j];

#pragma unroll
    for (int i = 0; i < 4; i++) {
        int n = node0 + lane * 4 + i;
        if (n < N) {
            float r[8];
#pragma unroll
            for (int j = 0; j < 8; j++) {
                float2 p = *(float2*)&acc[i][j];
                r[j] = fmaxf(p.x + p.y + bv[j], 0.0f);
            }
            *(float4*)(out + (size_t)n * TN + wid * 8)     = make_float4(r[0], r[1], r[2], r[3]);
            *(float4*)(out + (size_t)n * TN + wid * 8 + 4) = make_float4(r[4], r[5], r[6], r[7]);
        }
    }
}

// ---------------------------------------------------------------------------
// Layer-2 dual-output GEMM (K=128):  z = h @ Wl2^T,  r = h @ Wr2^T
// Cols 0..63 -> z, 64..127 -> r. No bias/relu (applied in gather64_add).
// ---------------------------------------------------------------------------
__global__ void __launch_bounds__(512, 1)
sage_gemm2_kernel(const float* __restrict__ h,
                  const float* __restrict__ Wl, const float* __restrict__ Wr,
                  float* __restrict__ z, float* __restrict__ r, int N) {
    constexpr int TM    = 128;
    constexpr int TN    = 128;
    constexpr int NT    = 512;
    constexpr int KC2   = 32;
    constexpr int WROW2 = TN + 2;
    constexpr int AROW2 = TM + 2;

    extern __shared__ float2 smem2[];
    float2* Wc = smem2;                          // [64][WROW2]
    float2* At = smem2 + 64 * WROW2;             // [2][KC2][AROW2]

    const int tid   = threadIdx.x;
    const int lane  = tid & 31;
    const int wid   = tid >> 5;
    const int node0 = blockIdx.x * TM;

    // Wc[k2][j] : j<64 -> Wl row j ; j>=64 -> Wr row j-64
    for (int idx = tid; idx < 64 * TN; idx += NT) {
        int j  = idx >> 6;
        int k2 = idx & 63;
        const float* srcw = (j < 64) ? (Wl + j * 128) : (Wr + (j - 64) * 128);
        Wc[k2 * WROW2 + j] = *(const float2*)(srcw + 2 * k2);
    }

    ull acc[4][8];
#pragma unroll
    for (int i = 0; i < 4; i++)
#pragma unroll
        for (int j = 0; j < 8; j++) acc[i][j] = 0ULL;

    auto loadA = [&](int buf, int kc) {
        float2* db = At + buf * (KC2 * AROW2);
#pragma unroll 4
        for (int idx = tid; idx < KC2 * TM; idx += NT) {
            int k2   = idx & (KC2 - 1);
            int node = idx >> 5;
            int n    = node0 + node;
            float2 v = make_float2(0.f, 0.f);
            if (n < N) v = *(const float2*)(h + (size_t)n * 128 + kc * 64 + 2 * k2);
            db[k2 * AROW2 + node] = v;
        }
    };

    loadA(0, 0);
    __syncthreads();

#pragma unroll 1
    for (int kc = 0; kc < 2; kc++) {
        int b = kc & 1;
        if (kc < 1) loadA(b ^ 1, kc + 1);
        const float2* Ab = At + b * (KC2 * AROW2);
        const float2* Wb = Wc + (kc * KC2) * WROW2;
#pragma unroll 4
        for (int kk2 = 0; kk2 < KC2; kk2++) {
            const float2* ar = Ab + kk2 * AROW2 + lane * 4;
            const float2* wr = Wb + kk2 * WROW2 + wid * 8;
            ull a[4], w[8];
            ulonglong2 t;
            t = *(const ulonglong2*)(ar);     a[0] = t.x; a[1] = t.y;
            t = *(const ulonglong2*)(ar + 2); a[2] = t.x; a[3] = t.y;
            t = *(const ulonglong2*)(wr);     w[0] = t.x; w[1] = t.y;
            t = *(const ulonglong2*)(wr + 2); w[2] = t.x; w[3] = t.y;
            t = *(const ulonglong2*)(wr + 4); w[4] = t.x; w[5] = t.y;
            t = *(const ulonglong2*)(wr + 6); w[6] = t.x; w[7] = t.y;
#pragma unroll
            for (int i = 0; i < 4; i++)
#pragma unroll
                for (int j = 0; j < 8; j++) ffma2(acc[i][j], a[i], w[j]);
        }
        __syncthreads();
    }

    const int col  = wid * 8;                    // 0..120
    float* outp    = (col < 64) ? z : r;
    const int colo = (col < 64) ? col : col - 64;

#pragma unroll
    for (int i = 0; i < 4; i++) {
        int n = node0 + lane * 4 + i;
        if (n < N) {
            float rr[8];
#pragma unroll
            for (int j = 0; j < 8; j++) {
                float2 p = *(float2*)&acc[i][j];
                rr[j] = p.x + p.y;
            }
            *(float4*)(outp + (size_t)n * 64 + colo)     = make_float4(rr[0], rr[1], rr[2], rr[3]);
            *(float4*)(outp + (size_t)n * 64 + colo + 4) = make_float4(rr[4], rr[5], rr[6], rr[7]);
        }
    }
}

// ---------------------------------------------------------------------------

extern "C" void kernel_launch(void* const* d_in, const int* in_sizes, int n_in,
                              void* d_out, int out_size) {
    const float* x   = (const float*)d_in[0];
    const void*  ei  = d_in[1];
    const float* Wl1 = (const float*)d_in[2];
    const float* bl1 = (const float*)d_in[3];
    const float* Wr1 = (const float*)d_in[4];
    const float* Wl2 = (const float*)d_in[5];
    const float* bl2 = (const float*)d_in[6];
    const float* Wr2 = (const float*)d_in[7];
    float* out = (float*)d_out;

    int N = in_sizes[0] / D_IN;
    int E = in_sizes[1] / 2;

    float *agg, *h;
    int *bin, *cnt, *off, *cur, *bsum;
    cudaGetSymbolAddress((void**)&agg,  g_agg);
    cudaGetSymbolAddress((void**)&h,    g_h);
    cudaGetSymbolAddress((void**)&bin,  g_bin);
    cudaGetSymbolAddress((void**)&cnt,  g_cnt);
    cudaGetSymbolAddress((void**)&off,  g_off);
    cudaGetSymbolAddress((void**)&cur,  g_cur);
    cudaGetSymbolAddress((void**)&bsum, g_bsum);

    float* zbuf = agg;                 // layer-2 z, reuses agg (done after GEMM1)
    float* rbuf = agg + (size_t)N * 64;

    constexpr int SMEM1 = (128 * 130 + 2 * 32 * 130) * 8;  // 199680 B
    constexpr int SMEM2 = (64  * 130 + 2 * 32 * 130) * 8;  // 133120 B
    cudaFuncSetAttribute(sage_gemm1_kernel, cudaFuncAttributeMaxDynamicSharedMemorySize, SMEM1);
    cudaFuncSetAttribute(sage_gemm2_kernel, cudaFuncAttributeMaxDynamicSharedMemorySize, SMEM2);

    const int TB = 256;
    int nbE = (E + TB - 1) / TB;
    int nbScan = (N + 1023) / 1024;

    // --- edge normalization + CSR binning (shared by both layers) ---
    detect_idx_kernel<<<1, 256>>>((const long long*)ei, E, (long long)N);
    cudaMemsetAsync(cnt, 0, (size_t)(N + 1) * sizeof(int));
    count_kernel<<<nbE, TB>>>(ei, cnt, E);
    scan_block_kernel<<<nbScan, 1024>>>(cnt, off, bsum, N);
    scan_bsum_kernel<<<1, 32>>>(bsum, nbScan);
    add_off_kernel<<<(N + TB - 1) / TB, TB>>>(off, bsum, N, E);
    cudaMemcpyAsync(cur, off, (size_t)(N + 1) * sizeof(int), cudaMemcpyDeviceToDevice);
    fill_kernel<<<nbE, TB>>>(ei, E, cur, bin);

    // --- layer 1 ---
    gather128_kernel<<<(N * 32 + TB - 1) / TB, TB>>>(
        (const ulonglong2*)x, off, bin, (float4*)agg, N);
    sage_gemm1_kernel<<<(N + 127) / 128, 512, SMEM1>>>(agg, x, Wl1, Wr1, bl1, h, N);

    // --- layer 2: transform first, then gather (linearity of mean) ---
    sage_gemm2_kernel<<<(N + 127) / 128, 512, SMEM2>>>(h, Wl2, Wr2, zbuf, rbuf, N);
    gather64_add_kernel<<<((N + 1) / 2 * 32 + TB - 1) / TB, TB>>>(
        (const ulonglong2*)zbuf, off, bin, (const float4*)rbuf, bl2, (float4*)out, N);
}

// round 7
// speedup vs baseline: 1.3240x; 1.0415x over previous
#include <cuda_runtime.h>
#include <cstdint>
#include <cstddef>

// ---------------------------------------------------------------------------
// GraphSAGE 2-layer, sm_103a.
//   h   = relu( scatter_mean(x, src->dst) @ Wl1^T + bl1 + x @ Wr1^T )
//   out =       scatter_mean(h, src->dst) @ Wl2^T + bl2 + h @ Wr2^T
// Round 6: conflict-free A-fragment LDS in both GEMMs (interleaved row map:
// thread row i -> lane + 32*i, LDS.64 contiguous across lanes); warp-shfl
// block-sum scan. Layer-2 keeps the linearity trick (z/r GEMM then 64-wide
// gather with fused epilogue). GEMMs: full-fp32 FFMA2 (fma.rn.f32x2).
// ---------------------------------------------------------------------------

#define MAX_N 100000
#define MAX_E 1600000
#define D_IN  128

typedef unsigned long long ull;

// Scratch (device globals: no allocation allowed in kernel_launch)
__device__ float g_agg[(size_t)MAX_N * 128];   // layer1 agg; layer2 reuses as z|r
__device__ float g_h[(size_t)MAX_N * 128];
__device__ int   g_bin[MAX_E];
__device__ int   g_cnt[MAX_N + 1];
__device__ int   g_off[MAX_N + 1];
__device__ int   g_cur[MAX_N + 1];
__device__ int   g_bsum[128];
__device__ int   g_is64;

__device__ __forceinline__ void ffma2(ull& d, ull a, ull b) {
    asm("fma.rn.f32x2 %0, %1, %2, %3;" : "=l"(d) : "l"(a), "l"(b), "l"(d));
}
__device__ __forceinline__ void fadd2(ull& d, ull a) {
    asm("add.rn.f32x2 %0, %1, %2;" : "=l"(d) : "l"(a), "l"(d));
}

// ---------------------------------------------------------------------------
// Edge-index dtype detection (int64 vs int32 payload).
// ---------------------------------------------------------------------------
__global__ void detect_idx_kernel(const long long* __restrict__ ei, int E, long long N) {
    __shared__ int bad;
    if (threadIdx.x == 0) bad = 0;
    __syncthreads();
    int i = threadIdx.x;
    if (i < E) {
        long long v = ei[i];
        if (v < 0 || v >= N) atomicAdd(&bad, 1);
    }
    __syncthreads();
    if (threadIdx.x == 0) g_is64 = (bad == 0) ? 1 : 0;
}

// ---------------------------------------------------------------------------
// CSR binning straight from edge_index: count -> scan -> fill
// ---------------------------------------------------------------------------
__global__ void count_kernel(const void* __restrict__ ei, int* __restrict__ cnt, int E) {
    int i = blockIdx.x * blockDim.x + threadIdx.x;
    if (i >= E) return;
    int d = g_is64 ? (int)((const long long*)ei)[(size_t)E + i]
                   : ((const int*)ei)[(size_t)E + i];
    atomicAdd(&cnt[d], 1);
}

__global__ void scan_block_kernel(const int* __restrict__ cnt, int* __restrict__ off,
                                  int* __restrict__ bsum, int N) {
    __shared__ int sm[1024];
    int tid = threadIdx.x;
    int gi  = blockIdx.x * 1024 + tid;
    int v   = (gi < N) ? cnt[gi] : 0;
    sm[tid] = v;
    __syncthreads();
#pragma unroll
    for (int s = 1; s < 1024; s <<= 1) {
        int t = (tid >= s) ? sm[tid - s] : 0;
        __syncthreads();
        sm[tid] += t;
        __syncthreads();
    }
    if (gi < N) off[gi] = sm[tid] - v;     // exclusive
    if (tid == 1023) bsum[blockIdx.x] = sm[1023];
}

// single-warp shfl scan over <=128 block sums (exclusive, in place)
__global__ void scan_bsum_kernel(int* __restrict__ bsum, int nb) {
    int lane  = threadIdx.x;
    int carry = 0;
    for (int base = 0; base < nb; base += 32) {
        int i = base + lane;
        int v = (i < nb) ? bsum[i] : 0;
        int orig = v;
#pragma unroll
        for (int s = 1; s < 32; s <<= 1) {
            int t = __shfl_up_sync(0xffffffffu, v, s);
            if (lane >= s) v += t;
        }
        if (i < nb) bsum[i] = carry + v - orig;
        carry += __shfl_sync(0xffffffffu, v, 31);
    }
}

__global__ void add_off_kernel(int* __restrict__ off, const int* __restrict__ bsum,
                               int N, int E) {
    int gi = blockIdx.x * blockDim.x + threadIdx.x;
    if (gi < N) off[gi] += bsum[gi >> 10];
    if (gi == 0) off[N] = E;
}

__global__ void fill_kernel(const void* __restrict__ ei, int E,
                            int* __restrict__ cur, int* __restrict__ bin) {
    int i = blockIdx.x * blockDim.x + threadIdx.x;
    if (i >= E) return;
    int s, d;
    if (g_is64) {
        const long long* p = (const long long*)ei;
        s = (int)p[i];
        d = (int)p[(size_t)E + i];
    } else {
        const int* p = (const int*)ei;
        s = p[i];
        d = p[(size_t)E + i];
    }
    int pos = atomicAdd(&cur[d], 1);
    bin[pos] = s;
}

// ---------------------------------------------------------------------------
// Gather-mean, 128-wide fp32 rows. One warp per node; lane owns 16B chunk.
// ---------------------------------------------------------------------------
__global__ void gather128_kernel(const ulonglong2* __restrict__ feat,  // 32 u2/row
                                 const int* __restrict__ off,
                                 const int* __restrict__ bin,
                                 float4* __restrict__ agg, int N) {
    int node = (blockIdx.x * blockDim.x + threadIdx.x) >> 5;
    int lane = threadIdx.x & 31;
    if (node >= N) return;
    int s0 = off[node], s1 = off[node + 1];
    ull a0 = 0, a1 = 0;
    int e = s0;
    for (; e + 4 <= s1; e += 4) {
        int i0 = bin[e], i1 = bin[e + 1], i2 = bin[e + 2], i3 = bin[e + 3];
        ulonglong2 v0 = feat[(size_t)i0 * 32 + lane];
        ulonglong2 v1 = feat[(size_t)i1 * 32 + lane];
        ulonglong2 v2 = feat[(size_t)i2 * 32 + lane];
        ulonglong2 v3 = feat[(size_t)i3 * 32 + lane];
        fadd2(a0, v0.x); fadd2(a1, v0.y);
        fadd2(a0, v1.x); fadd2(a1, v1.y);
        fadd2(a0, v2.x); fadd2(a1, v2.y);
        fadd2(a0, v3.x); fadd2(a1, v3.y);
    }
    for (; e < s1; e++) {
        ulonglong2 v = feat[(size_t)bin[e] * 32 + lane];
        fadd2(a0, v.x); fadd2(a1, v.y);
    }
    float sc = 1.0f / (float)max(s1 - s0, 1);
    float2 p0 = *(float2*)&a0, p1 = *(float2*)&a1;
    agg[(size_t)node * 32 + lane] =
        make_float4(p0.x * sc, p0.y * sc, p1.x * sc, p1.y * sc);
}

// ---------------------------------------------------------------------------
// Gather-mean over 64-wide z rows + fused epilogue: out = mean + bias + r.
// Half-warp (16 lanes) per node.
// ---------------------------------------------------------------------------
__global__ void gather64_add_kernel(const ulonglong2* __restrict__ z,   // 16 u2/row
                                    const int* __restrict__ off,
                                    const int* __restrict__ bin,
                                    const float4* __restrict__ r,       // 16 f4/row
                                    const float* __restrict__ bias,
                                    float4* __restrict__ out, int N) {
    int warp = (blockIdx.x * blockDim.x + threadIdx.x) >> 5;
    int lane = threadIdx.x & 31;
    int node = warp * 2 + (lane >> 4);
    int l16  = lane & 15;
    if (node >= N) return;
    int s0 = off[node], s1 = off[node + 1];
    ull a0 = 0, a1 = 0;
    int e = s0;
    for (; e + 4 <= s1; e += 4) {
        int i0 = bin[e], i1 = bin[e + 1], i2 = bin[e + 2], i3 = bin[e + 3];
        ulonglong2 v0 = z[(size_t)i0 * 16 + l16];
        ulonglong2 v1 = z[(size_t)i1 * 16 + l16];
        ulonglong2 v2 = z[(size_t)i2 * 16 + l16];
        ulonglong2 v3 = z[(size_t)i3 * 16 + l16];
        fadd2(a0, v0.x); fadd2(a1, v0.y);
        fadd2(a0, v1.x); fadd2(a1, v1.y);
        fadd2(a0, v2.x); fadd2(a1, v2.y);
        fadd2(a0, v3.x); fadd2(a1, v3.y);
    }
    for (; e < s1; e++) {
        ulonglong2 v = z[(size_t)bin[e] * 16 + l16];
        fadd2(a0, v.x); fadd2(a1, v.y);
    }
    float sc = 1.0f / (float)max(s1 - s0, 1);
    float2 p0 = *(float2*)&a0, p1 = *(float2*)&a1;
    float4 rv = r[(size_t)node * 16 + l16];
    float4 bv = __ldg((const float4*)bias + l16);
    out[(size_t)node * 16 + l16] =
        make_float4(p0.x * sc + bv.x + rv.x, p0.y * sc + bv.y + rv.y,
                    p1.x * sc + bv.z + rv.z, p1.y * sc + bv.w + rv.w);
}

// ---------------------------------------------------------------------------
// Layer-1 fused dual GEMM on packed fp32 FFMA2, K paired (K=256):
//   h = relu([agg | x] @ [Wl1 ; Wr1]^T + bl1)
// TM=128 nodes/CTA, 512 threads. Thread rows: lane + 32*i (conflict-free LDS).
// ---------------------------------------------------------------------------
__global__ void __launch_bounds__(512, 1)
sage_gemm1_kernel(const float* __restrict__ agg,
                  const float* __restrict__ xin,
                  const float* __restrict__ Wl, const float* __restrict__ Wr,
                  const float* __restrict__ bias,
                  float* __restrict__ out, int N) {
    constexpr int TM    = 128;
    constexpr int TN    = 128;
    constexpr int NT    = 512;
    constexpr int KC2   = 32;            // k-pairs per chunk (KC=64)
    constexpr int WROW2 = TN + 2;
    constexpr int AROW2 = TM + 2;

    extern __shared__ float2 smem2[];
    float2* Wc = smem2;                          // [128][WROW2]
    float2* At = smem2 + 128 * WROW2;            // [2][KC2][AROW2]

    const int tid   = threadIdx.x;
    const int lane  = tid & 31;
    const int wid   = tid >> 5;
    const int node0 = blockIdx.x * TM;

    for (int idx = tid; idx < 64 * TN; idx += NT) {
        int j  = idx >> 6;
        int k2 = idx & 63;
        Wc[k2 * WROW2 + j]        = *(const float2*)(Wl + j * 128 + 2 * k2);
        Wc[(64 + k2) * WROW2 + j] = *(const float2*)(Wr + j * 128 + 2 * k2);
    }

    ull acc[4][8];
#pragma unroll
    for (int i = 0; i < 4; i++)
#pragma unroll
        for (int j = 0; j < 8; j++) acc[i][j] = 0ULL;

    auto loadA = [&](int buf, int kc) {
        float2* db = At + buf * (KC2 * AROW2);
#pragma unroll 4
        for (int idx = tid; idx < KC2 * TM; idx += NT) {
            int k2   = idx & (KC2 - 1);
            int node = idx >> 5;
            int k    = kc * 64 + 2 * k2;
            int n    = node0 + node;
            float2 v = make_float2(0.f, 0.f);
            if (n < N) {
                v = (k < 128) ? *(const float2*)(agg + (size_t)n * 128 + k)
                              : *(const float2*)(xin + (size_t)n * 128 + (k - 128));
            }
            db[k2 * AROW2 + node] = v;
        }
    };

    loadA(0, 0);
    __syncthreads();

#pragma unroll 1
    for (int kc = 0; kc < 4; kc++) {
        int b = kc & 1;
        if (kc < 3) loadA(b ^ 1, kc + 1);
        const float2* Ab = At + b * (KC2 * AROW2);
        const float2* Wb = Wc + (kc * KC2) * WROW2;
#pragma unroll 4
        for (int kk2 = 0; kk2 < KC2; kk2++) {
            const float2* ar = Ab + kk2 * AROW2 + lane;   // 8B stride across lanes
            const float2* wr = Wb + kk2 * WROW2 + wid * 8;
            ull a[4], w[8];
            a[0] = *(const ull*)(ar);
            a[1] = *(const ull*)(ar + 32);
            a[2] = *(const ull*)(ar + 64);
            a[3] = *(const ull*)(ar + 96);
            ulonglong2 t;
            t = *(const ulonglong2*)(wr);     w[0] = t.x; w[1] = t.y;
            t = *(const ulonglong2*)(wr + 2); w[2] = t.x; w[3] = t.y;
            t = *(const ulonglong2*)(wr + 4); w[4] = t.x; w[5] = t.y;
            t = *(const ulonglong2*)(wr + 6); w[6] = t.x; w[7] = t.y;
#pragma unroll
            for (int i = 0; i < 4; i++)
#pragma unroll
                for (int j = 0; j < 8; j++) ffma2(acc[i][j], a[i], w[j]);
        }
        __syncthreads();
    }

    float bv[8];
#pragma unroll
    for (int j = 0; j < 8; j++) bv[j] = bias[wid * 8 + j];

#pragma unroll
    for (int i = 0; i < 4; i++) {
        int n = node0 + lane + 32 * i;
        if (n < N) {
            float r[8];
#pragma unroll
            for (int j = 0; j < 8; j++) {
                float2 p = *(float2*)&acc[i][j];
                r[j] = fmaxf(p.x + p.y + bv[j], 0.0f);
            }
            *(float4*)(out + (size_t)n * TN + wid * 8)     = make_float4(r[0], r[1], r[2], r[3]);
            *(float4*)(out + (size_t)n * TN + wid * 8 + 4) = make_float4(r[4], r[5], r[6], r[7]);
        }
    }
}

// ---------------------------------------------------------------------------
// Layer-2 dual-output GEMM (K=128):  z = h @ Wl2^T,  r = h @ Wr2^T
// Cols 0..63 -> z, 64..127 -> r. No bias/relu (applied in gather64_add).
// ---------------------------------------------------------------------------
__global__ void __launch_bounds__(512, 1)
sage_gemm2_kernel(const float* __restrict__ h,
                  const float* __restrict__ Wl, const float* __restrict__ Wr,
                  float* __restrict__ z, float* __restrict__ r, int N) {
    constexpr int TM    = 128;
    constexpr int TN    = 128;
    constexpr int NT    = 512;
    constexpr int KC2   = 32;
    constexpr int WROW2 = TN + 2;
    constexpr int AROW2 = TM + 2;

    extern __shared__ float2 smem2[];
    float2* Wc = smem2;                          // [64][WROW2]
    float2* At = smem2 + 64 * WROW2;             // [2][KC2][AROW2]

    const int tid   = threadIdx.x;
    const int lane  = tid & 31;
    const int wid   = tid >> 5;
    const int node0 = blockIdx.x * TM;

    // Wc[k2][j] : j<64 -> Wl row j ; j>=64 -> Wr row j-64
    for (int idx = tid; idx < 64 * TN; idx += NT) {
        int j  = idx >> 6;
        int k2 = idx & 63;
        const float* srcw = (j < 64) ? (Wl + j * 128) : (Wr + (j - 64) * 128);
        Wc[k2 * WROW2 + j] = *(const float2*)(srcw + 2 * k2);
    }

    ull acc[4][8];
#pragma unroll
    for (int i = 0; i < 4; i++)
#pragma unroll
        for (int j = 0; j < 8; j++) acc[i][j] = 0ULL;

    auto loadA = [&](int buf, int kc) {
        float2* db = At + buf * (KC2 * AROW2);
#pragma unroll 4
        for (int idx = tid; idx < KC2 * TM; idx += NT) {
            int k2   = idx & (KC2 - 1);
            int node = idx >> 5;
            int n    = node0 + node;
            float2 v = make_float2(0.f, 0.f);
            if (n < N) v = *(const float2*)(h + (size_t)n * 128 + kc * 64 + 2 * k2);
            db[k2 * AROW2 + node] = v;
        }
    };

    loadA(0, 0);
    __syncthreads();

#pragma unroll 1
    for (int kc = 0; kc < 2; kc++) {
        int b = kc & 1;
        if (kc < 1) loadA(b ^ 1, kc + 1);
        const float2* Ab = At + b * (KC2 * AROW2);
        const float2* Wb = Wc + (kc * KC2) * WROW2;
#pragma unroll 4
        for (int kk2 = 0; kk2 < KC2; kk2++) {
            const float2* ar = Ab + kk2 * AROW2 + lane;
            const float2* wr = Wb + kk2 * WROW2 + wid * 8;
            ull a[4], w[8];
            a[0] = *(const ull*)(ar);
            a[1] = *(const ull*)(ar + 32);
            a[2] = *(const ull*)(ar + 64);
            a[3] = *(const ull*)(ar + 96);
            ulonglong2 t;
            t = *(const ulonglong2*)(wr);     w[0] = t.x; w[1] = t.y;
            t = *(const ulonglong2*)(wr + 2); w[2] = t.x; w[3] = t.y;
            t = *(const ulonglong2*)(wr + 4); w[4] = t.x; w[5] = t.y;
            t = *(const ulonglong2*)(wr + 6); w[6] = t.x; w[7] = t.y;
#pragma unroll
            for (int i = 0; i < 4; i++)
#pragma unroll
                for (int j = 0; j < 8; j++) ffma2(acc[i][j], a[i], w[j]);
        }
        __syncthreads();
    }

    const int col  = wid * 8;                    // 0..120
    float* outp    = (col < 64) ? z : r;
    const int colo = (col < 64) ? col : col - 64;

#pragma unroll
    for (int i = 0; i < 4; i++) {
        int n = node0 + lane + 32 * i;
        if (n < N) {
            float rr[8];
#pragma unroll
            for (int j = 0; j < 8; j++) {
                float2 p = *(float2*)&acc[i][j];
                rr[j] = p.x + p.y;
            }
            *(float4*)(outp + (size_t)n * 64 + colo)     = make_float4(rr[0], rr[1], rr[2], rr[3]);
            *(float4*)(outp + (size_t)n * 64 + colo + 4) = make_float4(rr[4], rr[5], rr[6], rr[7]);
        }
    }
}

// ---------------------------------------------------------------------------

extern "C" void kernel_launch(void* const* d_in, const int* in_sizes, int n_in,
                              void* d_out, int out_size) {
    const float* x   = (const float*)d_in[0];
    const void*  ei  = d_in[1];
    const float* Wl1 = (const float*)d_in[2];
    const float* bl1 = (const float*)d_in[3];
    const float* Wr1 = (const float*)d_in[4];
    const float* Wl2 = (const float*)d_in[5];
    const float* bl2 = (const float*)d_in[6];
    const float* Wr2 = (const float*)d_in[7];
    float* out = (float*)d_out;

    int N = in_sizes[0] / D_IN;
    int E = in_sizes[1] / 2;

    float *agg, *h;
    int *bin, *cnt, *off, *cur, *bsum;
    cudaGetSymbolAddress((void**)&agg,  g_agg);
    cudaGetSymbolAddress((void**)&h,    g_h);
    cudaGetSymbolAddress((void**)&bin,  g_bin);
    cudaGetSymbolAddress((void**)&cnt,  g_cnt);
    cudaGetSymbolAddress((void**)&off,  g_off);
    cudaGetSymbolAddress((void**)&cur,  g_cur);
    cudaGetSymbolAddress((void**)&bsum, g_bsum);

    float* zbuf = agg;                 // layer-2 z, reuses agg (done after GEMM1)
    float* rbuf = agg + (size_t)N * 64;

    constexpr int SMEM1 = (128 * 130 + 2 * 32 * 130) * 8;  // 199680 B
    constexpr int SMEM2 = (64  * 130 + 2 * 32 * 130) * 8;  // 133120 B
    cudaFuncSetAttribute(sage_gemm1_kernel, cudaFuncAttributeMaxDynamicSharedMemorySize, SMEM1);
    cudaFuncSetAttribute(sage_gemm2_kernel, cudaFuncAttributeMaxDynamicSharedMemorySize, SMEM2);

    const int TB = 256;
    int nbE = (E + TB - 1) / TB;
    int nbScan = (N + 1023) / 1024;

    // --- edge normalization + CSR binning (shared by both layers) ---
    detect_idx_kernel<<<1, 256>>>((const long long*)ei, E, (long long)N);
    cudaMemsetAsync(cnt, 0, (size_t)(N + 1) * sizeof(int));
    count_kernel<<<nbE, TB>>>(ei, cnt, E);
    scan_block_kernel<<<nbScan, 1024>>>(cnt, off, bsum, N);
    scan_bsum_kernel<<<1, 32>>>(bsum, nbScan);
    add_off_kernel<<<(N + TB - 1) / TB, TB>>>(off, bsum, N, E);
    cudaMemcpyAsync(cur, off, (size_t)(N + 1) * sizeof(int), cudaMemcpyDeviceToDevice);
    fill_kernel<<<nbE, TB>>>(ei, E, cur, bin);

    // --- layer 1 ---
    gather128_kernel<<<(N * 32 + TB - 1) / TB, TB>>>(
        (const ulonglong2*)x, off, bin, (float4*)agg, N);
    sage_gemm1_kernel<<<(N + 127) / 128, 512, SMEM1>>>(agg, x, Wl1, Wr1, bl1, h, N);

    // --- layer 2: transform first, then gather (linearity of mean) ---
    sage_gemm2_kernel<<<(N + 127) / 128, 512, SMEM2>>>(h, Wl2, Wr2, zbuf, rbuf, N);
    gather64_add_kernel<<<((N + 1) / 2 * 32 + TB - 1) / TB, TB>>>(
        (const ulonglong2*)zbuf, off, bin, (const float4*)rbuf, bl2, (float4*)out, N);
}

// round 9
// speedup vs baseline: 1.4839x; 1.1207x over previous
#include <cuda_runtime.h>
#include <cstdint>
#include <cstddef>

// ---------------------------------------------------------------------------
// GraphSAGE 2-layer, sm_103a.
//   h   = relu( scatter_mean(x, src->dst) @ Wl1^T + bl1 + x @ Wr1^T )
//   out =       scatter_mean(h, src->dst) @ Wl2^T + bl2 + h @ Wr2^T
// Round 8: fix R7 alignment trap — per-region smem strides:
//   A tiles RSA=133 (odd ok: 8B fragment loads; 2-way staging STS)
//   W tiles RSW=130 (even: 16B-aligned ulonglong2 fragment loads)
// Keeps: float4 staging, single-stage GEMM2, int4 index loads, no memcpy.
// FFMA2 (fma.rn.f32x2) fp32 throughout.
// ---------------------------------------------------------------------------

#define MAX_N 100000
#define MAX_E 1600000
#define D_IN  128

typedef unsigned long long ull;

__device__ float g_agg[(size_t)MAX_N * 128];   // layer1 agg; layer2 reuses as z|r
__device__ float g_h[(size_t)MAX_N * 128];
__device__ int   g_bin[MAX_E];
__device__ int   g_cnt[MAX_N + 1];
__device__ int   g_off[MAX_N + 1];
__device__ int   g_cur[MAX_N + 1];
__device__ int   g_bsum[128];
__device__ int   g_is64;

__device__ __forceinline__ void ffma2(ull& d, ull a, ull b) {
    asm("fma.rn.f32x2 %0, %1, %2, %3;" : "=l"(d) : "l"(a), "l"(b), "l"(d));
}
__device__ __forceinline__ void fadd2(ull& d, ull a) {
    asm("add.rn.f32x2 %0, %1, %2;" : "=l"(d) : "l"(a), "l"(d));
}

// ---------------------------------------------------------------------------
__global__ void detect_idx_kernel(const long long* __restrict__ ei, int E, long long N) {
    __shared__ int bad;
    if (threadIdx.x == 0) bad = 0;
    __syncthreads();
    int i = threadIdx.x;
    if (i < E) {
        long long v = ei[i];
        if (v < 0 || v >= N) atomicAdd(&bad, 1);
    }
    __syncthreads();
    if (threadIdx.x == 0) g_is64 = (bad == 0) ? 1 : 0;
}

// ---------------------------------------------------------------------------
// CSR binning: count -> scan -> fill
// ---------------------------------------------------------------------------
__global__ void count_kernel(const void* __restrict__ ei, int* __restrict__ cnt, int E) {
    int i = blockIdx.x * blockDim.x + threadIdx.x;
    if (i >= E) return;
    int d = g_is64 ? (int)((const long long*)ei)[(size_t)E + i]
                   : ((const int*)ei)[(size_t)E + i];
    atomicAdd(&cnt[d], 1);
}

__global__ void scan_block_kernel(const int* __restrict__ cnt, int* __restrict__ off,
                                  int* __restrict__ bsum, int N) {
    __shared__ int sm[1024];
    int tid = threadIdx.x;
    int gi  = blockIdx.x * 1024 + tid;
    int v   = (gi < N) ? cnt[gi] : 0;
    sm[tid] = v;
    __syncthreads();
#pragma unroll
    for (int s = 1; s < 1024; s <<= 1) {
        int t = (tid >= s) ? sm[tid - s] : 0;
        __syncthreads();
        sm[tid] += t;
        __syncthreads();
    }
    if (gi < N) off[gi] = sm[tid] - v;     // exclusive
    if (tid == 1023) bsum[blockIdx.x] = sm[1023];
}

__global__ void scan_bsum_kernel(int* __restrict__ bsum, int nb) {
    int lane  = threadIdx.x;
    int carry = 0;
    for (int base = 0; base < nb; base += 32) {
        int i = base + lane;
        int v = (i < nb) ? bsum[i] : 0;
        int orig = v;
#pragma unroll
        for (int s = 1; s < 32; s <<= 1) {
            int t = __shfl_up_sync(0xffffffffu, v, s);
            if (lane >= s) v += t;
        }
        if (i < nb) bsum[i] = carry + v - orig;
        carry += __shfl_sync(0xffffffffu, v, 31);
    }
}

__global__ void add_off_kernel(int* __restrict__ off, int* __restrict__ cur,
                               const int* __restrict__ bsum, int N, int E) {
    int gi = blockIdx.x * blockDim.x + threadIdx.x;
    if (gi < N) {
        int v = off[gi] + bsum[gi >> 10];
        off[gi] = v;
        cur[gi] = v;
    }
    if (gi == 0) { off[N] = E; cur[N] = E; }
}

__global__ void fill_kernel(const void* __restrict__ ei, int E,
                            int* __restrict__ cur, int* __restrict__ bin) {
    int i = blockIdx.x * blockDim.x + threadIdx.x;
    if (i >= E) return;
    int s, d;
    if (g_is64) {
        const long long* p = (const long long*)ei;
        s = (int)p[i];
        d = (int)p[(size_t)E + i];
    } else {
        const int* p = (const int*)ei;
        s = p[i];
        d = p[(size_t)E + i];
    }
    int pos = atomicAdd(&cur[d], 1);
    bin[pos] = s;
}

// ---------------------------------------------------------------------------
// Gather-mean, 128-wide rows. One warp per node; lane owns 16B chunk.
// int4 index loads on the aligned middle segment.
// ---------------------------------------------------------------------------
__global__ void gather128_kernel(const ulonglong2* __restrict__ feat,  // 32 u2/row
                                 const int* __restrict__ off,
                                 const int* __restrict__ bin,
                                 float4* __restrict__ agg, int N) {
    int node = (blockIdx.x * blockDim.x + threadIdx.x) >> 5;
    int lane = threadIdx.x & 31;
    if (node >= N) return;
    int s0 = off[node], s1 = off[node + 1];
    ull a0 = 0, a1 = 0;
    int e = s0;
    int ea = (s0 + 3) & ~3;
    for (; e < s1 && e < ea; e++) {
        ulonglong2 v = feat[(size_t)bin[e] * 32 + lane];
        fadd2(a0, v.x); fadd2(a1, v.y);
    }
    for (; e + 4 <= s1; e += 4) {
        int4 q = *(const int4*)(bin + e);
        ulonglong2 v0 = feat[(size_t)q.x * 32 + lane];
        ulonglong2 v1 = feat[(size_t)q.y * 32 + lane];
        ulonglong2 v2 = feat[(size_t)q.z * 32 + lane];
        ulonglong2 v3 = feat[(size_t)q.w * 32 + lane];
        fadd2(a0, v0.x); fadd2(a1, v0.y);
        fadd2(a0, v1.x); fadd2(a1, v1.y);
        fadd2(a0, v2.x); fadd2(a1, v2.y);
        fadd2(a0, v3.x); fadd2(a1, v3.y);
    }
    for (; e < s1; e++) {
        ulonglong2 v = feat[(size_t)bin[e] * 32 + lane];
        fadd2(a0, v.x); fadd2(a1, v.y);
    }
    float sc = 1.0f / (float)max(s1 - s0, 1);
    float2 p0 = *(float2*)&a0, p1 = *(float2*)&a1;
    agg[(size_t)node * 32 + lane] =
        make_float4(p0.x * sc, p0.y * sc, p1.x * sc, p1.y * sc);
}

// ---------------------------------------------------------------------------
// Gather-mean over 64-wide z rows + fused epilogue: out = mean + bias + r.
// Half-warp per node; int4 index loads.
// ---------------------------------------------------------------------------
__global__ void gather64_add_kernel(const ulonglong2* __restrict__ z,   // 16 u2/row
                                    const int* __restrict__ off,
                                    const int* __restrict__ bin,
                                    const float4* __restrict__ r,       // 16 f4/row
                                    const float* __restrict__ bias,
                                    float4* __restrict__ out, int N) {
    int warp = (blockIdx.x * blockDim.x + threadIdx.x) >> 5;
    int lane = threadIdx.x & 31;
    int node = warp * 2 + (lane >> 4);
    int l16  = lane & 15;
    if (node >= N) return;
    int s0 = off[node], s1 = off[node + 1];
    ull a0 = 0, a1 = 0;
    int e = s0;
    int ea = (s0 + 3) & ~3;
    for (; e < s1 && e < ea; e++) {
        ulonglong2 v = z[(size_t)bin[e] * 16 + l16];
        fadd2(a0, v.x); fadd2(a1, v.y);
    }
    for (; e + 4 <= s1; e += 4) {
        int4 q = *(const int4*)(bin + e);
        ulonglong2 v0 = z[(size_t)q.x * 16 + l16];
        ulonglong2 v1 = z[(size_t)q.y * 16 + l16];
        ulonglong2 v2 = z[(size_t)q.z * 16 + l16];
        ulonglong2 v3 = z[(size_t)q.w * 16 + l16];
        fadd2(a0, v0.x); fadd2(a1, v0.y);
        fadd2(a0, v1.x); fadd2(a1, v1.y);
        fadd2(a0, v2.x); fadd2(a1, v2.y);
        fadd2(a0, v3.x); fadd2(a1, v3.y);
    }
    for (; e < s1; e++) {
        ulonglong2 v = z[(size_t)bin[e] * 16 + l16];
        fadd2(a0, v.x); fadd2(a1, v.y);
    }
    float sc = 1.0f / (float)max(s1 - s0, 1);
    float2 p0 = *(float2*)&a0, p1 = *(float2*)&a1;
    float4 rv = r[(size_t)node * 16 + l16];
    float4 bv = __ldg((const float4*)bias + l16);
    out[(size_t)node * 16 + l16] =
        make_float4(p0.x * sc + bv.x + rv.x, p0.y * sc + bv.y + rv.y,
                    p1.x * sc + bv.z + rv.z, p1.y * sc + bv.w + rv.w);
}

// ---------------------------------------------------------------------------
// Layer-1 fused dual GEMM (K=256, k-paired FFMA2):
//   h = relu([agg | x] @ [Wl1 ; Wr1]^T + bl1)
// TM=128, 512 thr, thread rows lane+32*i.
// W rows: stride RSW=130 f2 (even -> 16B-aligned fragment loads).
// A rows: stride RSA=133 f2 (odd  -> 2-way staging STS; 8B fragment loads).
// ---------------------------------------------------------------------------
__global__ void __launch_bounds__(512, 1)
sage_gemm1_kernel(const float* __restrict__ agg,
                  const float* __restrict__ xin,
                  const float* __restrict__ Wl, const float* __restrict__ Wr,
                  const float* __restrict__ bias,
                  float* __restrict__ out, int N) {
    constexpr int TM  = 128;
    constexpr int TN  = 128;
    constexpr int NT  = 512;
    constexpr int KC2 = 32;            // k-pairs per chunk
    constexpr int RSW = 130;           // W row stride (float2), even
    constexpr int RSA = 133;           // A row stride (float2), odd

    extern __shared__ float2 smem2[];
    float2* Wc = smem2;                          // [128][RSW]
    float2* At = smem2 + 128 * RSW;              // [2][KC2][RSA]

    const int tid   = threadIdx.x;
    const int lane  = tid & 31;
    const int wid   = tid >> 5;
    const int node0 = blockIdx.x * TM;

    for (int idx = tid; idx < 64 * TN; idx += NT) {
        int j  = idx >> 6;
        int k2 = idx & 63;
        Wc[k2 * RSW + j]        = *(const float2*)(Wl + j * 128 + 2 * k2);
        Wc[(64 + k2) * RSW + j] = *(const float2*)(Wr + j * 128 + 2 * k2);
    }

    ull acc[4][8];
#pragma unroll
    for (int i = 0; i < 4; i++)
#pragma unroll
        for (int j = 0; j < 8; j++) acc[i][j] = 0ULL;

    // chunk kc covers k-pairs kc*32..+31 (k = kc*64..+63) — single source
    auto loadA = [&](int buf, int kc) {
        const float* src = (kc < 2) ? (agg + kc * 64) : (xin + (kc - 2) * 64);
        float2* db = At + buf * (KC2 * RSA);
#pragma unroll 4
        for (int idx = tid; idx < (KC2 * TM) / 2; idx += NT) {
            int k2p  = idx & 15;        // float4 = 2 k-pairs
            int node = idx >> 4;
            int n    = node0 + node;
            float4 v = make_float4(0.f, 0.f, 0.f, 0.f);
            if (n < N) v = *(const float4*)(src + (size_t)n * 128 + 4 * k2p);
            db[(2 * k2p) * RSA + node]     = make_float2(v.x, v.y);
            db[(2 * k2p + 1) * RSA + node] = make_float2(v.z, v.w);
        }
    };

    loadA(0, 0);
    __syncthreads();   // covers Wc too

#pragma unroll 1
    for (int kc = 0; kc < 4; kc++) {
        int b = kc & 1;
        if (kc < 3) loadA(b ^ 1, kc + 1);
        const float2* Ab = At + b * (KC2 * RSA);
        const float2* Wb = Wc + (kc * KC2) * RSW;
#pragma unroll 4
        for (int kk2 = 0; kk2 < KC2; kk2++) {
            const float2* ar = Ab + kk2 * RSA + lane;
            const float2* wr = Wb + kk2 * RSW + wid * 8;
            ull a[4], w[8];
            a[0] = *(const ull*)(ar);
            a[1] = *(const ull*)(ar + 32);
            a[2] = *(const ull*)(ar + 64);
            a[3] = *(const ull*)(ar + 96);
            ulonglong2 t;
            t = *(const ulonglong2*)(wr);     w[0] = t.x; w[1] = t.y;
            t = *(const ulonglong2*)(wr + 2); w[2] = t.x; w[3] = t.y;
            t = *(const ulonglong2*)(wr + 4); w[4] = t.x; w[5] = t.y;
            t = *(const ulonglong2*)(wr + 6); w[6] = t.x; w[7] = t.y;
#pragma unroll
            for (int i = 0; i < 4; i++)
#pragma unroll
                for (int j = 0; j < 8; j++) ffma2(acc[i][j], a[i], w[j]);
        }
        __syncthreads();
    }

    float bv[8];
#pragma unroll
    for (int j = 0; j < 8; j++) bv[j] = bias[wid * 8 + j];

#pragma unroll
    for (int i = 0; i < 4; i++) {
        int n = node0 + lane + 32 * i;
        if (n < N) {
            float r[8];
#pragma unroll
            for (int j = 0; j < 8; j++) {
                float2 p = *(float2*)&acc[i][j];
                r[j] = fmaxf(p.x + p.y + bv[j], 0.0f);
            }
            *(float4*)(out + (size_t)n * TN + wid * 8)     = make_float4(r[0], r[1], r[2], r[3]);
            *(float4*)(out + (size_t)n * TN + wid * 8 + 4) = make_float4(r[4], r[5], r[6], r[7]);
        }
    }
}

// ---------------------------------------------------------------------------
// Layer-2 dual-output GEMM (K=128):  z = h @ Wl2^T,  r = h @ Wr2^T
// Fully smem-resident (W 64 k-pairs + A 64 k-pairs), single stage, one sync.
// ---------------------------------------------------------------------------
__global__ void __launch_bounds__(512, 1)
sage_gemm2_kernel(const float* __restrict__ h,
                  const float* __restrict__ Wl, const float* __restrict__ Wr,
                  float* __restrict__ z, float* __restrict__ r, int N) {
    constexpr int TM  = 128;
    constexpr int TN  = 128;
    constexpr int NT  = 512;
    constexpr int RSW = 130;
    constexpr int RSA = 133;

    extern __shared__ float2 smem2[];
    float2* Wc = smem2;                          // [64][RSW]
    float2* Ac = smem2 + 64 * RSW;               // [64][RSA]

    const int tid   = threadIdx.x;
    const int lane  = tid & 31;
    const int wid   = tid >> 5;
    const int node0 = blockIdx.x * TM;

    // Wc[k2][j] : j<64 -> Wl row j ; j>=64 -> Wr row j-64
    for (int idx = tid; idx < 64 * TN; idx += NT) {
        int j  = idx >> 6;
        int k2 = idx & 63;
        const float* srcw = (j < 64) ? (Wl + j * 128) : (Wr + (j - 64) * 128);
        Wc[k2 * RSW + j] = *(const float2*)(srcw + 2 * k2);
    }

    // A: all 64 k-pairs resident. float4 loads (2 k-pairs each).
#pragma unroll 4
    for (int idx = tid; idx < (64 * TM) / 2; idx += NT) {
        int k2p  = idx & 31;
        int node = idx >> 5;
        int n    = node0 + node;
        float4 v = make_float4(0.f, 0.f, 0.f, 0.f);
        if (n < N) v = *(const float4*)(h + (size_t)n * 128 + 4 * k2p);
        Ac[(2 * k2p) * RSA + node]     = make_float2(v.x, v.y);
        Ac[(2 * k2p + 1) * RSA + node] = make_float2(v.z, v.w);
    }

    ull acc[4][8];
#pragma unroll
    for (int i = 0; i < 4; i++)
#pragma unroll
        for (int j = 0; j < 8; j++) acc[i][j] = 0ULL;

    __syncthreads();

#pragma unroll 4
    for (int kk2 = 0; kk2 < 64; kk2++) {
        const float2* ar = Ac + kk2 * RSA + lane;
        const float2* wr = Wc + kk2 * RSW + wid * 8;
        ull a[4], w[8];
        a[0] = *(const ull*)(ar);
        a[1] = *(const ull*)(ar + 32);
        a[2] = *(const ull*)(ar + 64);
        a[3] = *(const ull*)(ar + 96);
        ulonglong2 t;
        t = *(const ulonglong2*)(wr);     w[0] = t.x; w[1] = t.y;
        t = *(const ulonglong2*)(wr + 2); w[2] = t.x; w[3] = t.y;
        t = *(const ulonglong2*)(wr + 4); w[4] = t.x; w[5] = t.y;
        t = *(const ulonglong2*)(wr + 6); w[6] = t.x; w[7] = t.y;
#pragma unroll
        for (int i = 0; i < 4; i++)
#pragma unroll
            for (int j = 0; j < 8; j++) ffma2(acc[i][j], a[i], w[j]);
    }

    const int col  = wid * 8;                    // 0..120
    float* outp    = (col < 64) ? z : r;
    const int colo = (col < 64) ? col : col - 64;

#pragma unroll
    for (int i = 0; i < 4; i++) {
        int n = node0 + lane + 32 * i;
        if (n < N) {
            float rr[8];
#pragma unroll
            for (int j = 0; j < 8; j++) {
                float2 p = *(float2*)&acc[i][j];
                rr[j] = p.x + p.y;
            }
            *(float4*)(outp + (size_t)n * 64 + colo)     = make_float4(rr[0], rr[1], rr[2], rr[3]);
            *(float4*)(outp + (size_t)n * 64 + colo + 4) = make_float4(rr[4], rr[5], rr[6], rr[7]);
        }
    }
}

// ---------------------------------------------------------------------------

extern "C" void kernel_launch(void* const* d_in, const int* in_sizes, int n_in,
                              void* d_out, int out_size) {
    const float* x   = (const float*)d_in[0];
    const void*  ei  = d_in[1];
    const float* Wl1 = (const float*)d_in[2];
    const float* bl1 = (const float*)d_in[3];
    const float* Wr1 = (const float*)d_in[4];
    const float* Wl2 = (const float*)d_in[5];
    const float* bl2 = (const float*)d_in[6];
    const float* Wr2 = (const float*)d_in[7];
    float* out = (float*)d_out;

    int N = in_sizes[0] / D_IN;
    int E = in_sizes[1] / 2;

    float *agg, *h;
    int *bin, *cnt, *off, *cur, *bsum;
    cudaGetSymbolAddress((void**)&agg,  g_agg);
    cudaGetSymbolAddress((void**)&h,    g_h);
    cudaGetSymbolAddress((void**)&bin,  g_bin);
    cudaGetSymbolAddress((void**)&cnt,  g_cnt);
    cudaGetSymbolAddress((void**)&off,  g_off);
    cudaGetSymbolAddress((void**)&cur,  g_cur);
    cudaGetSymbolAddress((void**)&bsum, g_bsum);

    float* zbuf = agg;
    float* rbuf = agg + (size_t)N * 64;

    constexpr int SMEM1 = (128 * 130 + 2 * 32 * 133) * 8;  // 201216 B
    constexpr int SMEM2 = (64 * 130 + 64 * 133) * 8;       // 134656 B
    cudaFuncSetAttribute(sage_gemm1_kernel, cudaFuncAttributeMaxDynamicSharedMemorySize, SMEM1);
    cudaFuncSetAttribute(sage_gemm2_kernel, cudaFuncAttributeMaxDynamicSharedMemorySize, SMEM2);

    const int TB = 256;
    int nbE = (E + TB - 1) / TB;
    int nbScan = (N + 1023) / 1024;

    // --- edge normalization + CSR binning (shared by both layers) ---
    detect_idx_kernel<<<1, 256>>>((const long long*)ei, E, (long long)N);
    cudaMemsetAsync(cnt, 0, (size_t)(N + 1) * sizeof(int));
    count_kernel<<<nbE, TB>>>(ei, cnt, E);
    scan_block_kernel<<<nbScan, 1024>>>(cnt, off, bsum, N);
    scan_bsum_kernel<<<1, 32>>>(bsum, nbScan);
    add_off_kernel<<<(N + TB - 1) / TB, TB>>>(off, cur, bsum, N, E);
    fill_kernel<<<nbE, TB>>>(ei, E, cur, bin);

    // --- layer 1 ---
    gather128_kernel<<<(N * 32 + TB - 1) / TB, TB>>>(
        (const ulonglong2*)x, off, bin, (float4*)agg, N);
    sage_gemm1_kernel<<<(N + 127) / 128, 512, SMEM1>>>(agg, x, Wl1, Wr1, bl1, h, N);

    // --- layer 2: transform first, then gather (linearity of mean) ---
    sage_gemm2_kernel<<<(N + 127) / 128, 512, SMEM2>>>(h, Wl2, Wr2, zbuf, rbuf, N);
    gather64_add_kernel<<<((N + 1) / 2 * 32 + TB - 1) / TB, TB>>>(
        (const ulonglong2*)zbuf, off, bin, (const float4*)rbuf, bl2, (float4*)out, N);
}